// round 12
// baseline (speedup 1.0000x reference)
#include <cuda_runtime.h>

#define FULL 0xFFFFFFFFu

// Problem shape (fixed): N=1, L=S=512, H=8, D=M=32
constexpr int H = 8;
constexpr int NCH = 16;              // 32-row chunks per head
constexpr int MATS = 3 * 1024 + 32;  // KK(1024) SQQ(1024) KV(1024) Ksum(32)
constexpr float K_SCALE = 0.05892556509887896f; // 1/(3*sqrt(32))

// Contiguous partial layout: g_part[cta][elem]  (cta = c*8 + h)
__device__ __align__(16) float g_part[NCH * H * MATS];
__device__ __align__(16) float g_mats[H * MATS];
__device__ __align__(16) float g_Qn[512 * H * 32];
__device__ __align__(16) float g_Kn[512 * H * 32];

// ---------------------------------------------------------------------------
// K1: 128 CTAs x 512 thr (16 warps/SM). LN + partial matrices.
// Groups: KK(0-127), SQQ(128-255), KV(256-383), stores+Ksum(384-511).
// ---------------------------------------------------------------------------
__global__ __launch_bounds__(512) void k1_build(
        const float* __restrict__ q, const float* __restrict__ k,
        const float* __restrict__ v, const float* __restrict__ klen) {
    __shared__ __align__(16) float sQ[32][36];
    __shared__ __align__(16) float sK[32][36];
    __shared__ __align__(16) float sV[32][36];

    int bx = blockIdx.x;
    int h = bx & 7, c = bx >> 3;
    int tid = threadIdx.x, lane = tid & 31, w = tid >> 5;

    // ---- load raw tiles: 768 float4 over 512 threads ----
    #pragma unroll
    for (int i = tid; i < 768; i += 512) {
        int ten = i >> 8, idx = i & 255;
        int r4 = idx >> 3, c4 = (idx & 7) * 4;
        int g = ((c * 32 + r4) * H + h) * 32 + c4;
        const float* src = (ten == 0) ? q : (ten == 1) ? k : v;
        float (*dst)[36] = (ten == 0) ? sQ : (ten == 1) ? sK : sV;
        *(float4*)&dst[r4][c4] = *(const float4*)&src[g];
    }
    __syncthreads();

    // ---- LayerNorm: warp w -> rows w, w+16 ----
    #pragma unroll
    for (int rr = 0; rr < 2; rr++) {
        int r = w + rr * 16;
        float x = sQ[r][lane], y = sK[r][lane];
        float sx = x, sxx = x * x, sy = y, syy = y * y;
        #pragma unroll
        for (int o = 16; o; o >>= 1) {
            sx  += __shfl_xor_sync(FULL, sx,  o);
            sxx += __shfl_xor_sync(FULL, sxx, o);
            sy  += __shfl_xor_sync(FULL, sy,  o);
            syy += __shfl_xor_sync(FULL, syy, o);
        }
        float muq = sx * (1.0f / 32.0f);
        float vq  = fmaf(-muq, muq, sxx * (1.0f / 32.0f));
        sQ[r][lane] = (x - muq) * rsqrtf(vq + 1e-5f);
        float muk = sy * (1.0f / 32.0f);
        float vk  = fmaf(-muk, muk, syy * (1.0f / 32.0f));
        sK[r][lane] = (y - muk) * rsqrtf(vk + 1e-5f) * (K_SCALE * klen[c * 32 + r]);
    }
    __syncthreads();

    int grp = tid >> 7, t = tid & 127;
    float* outp = &g_part[(size_t)bx * MATS];
    if (grp < 3) {
        // C[a][b] = sum_r X[r][a] * Y[r][b], 4x2 tile per thread
        const float (*X)[36] = (grp == 0) ? sK : (grp == 1) ? sQ : sK;
        const float (*Y)[36] = (grp == 0) ? sK : (grp == 1) ? sQ : sV;
        int a0 = (t & 7) * 4, b0 = (t >> 3) * 2;
        float acc[4][2] = {};
        #pragma unroll 4
        for (int r = 0; r < 32; r++) {
            float4 xa = *(const float4*)&X[r][a0];
            float2 yb = *(const float2*)&Y[r][b0];
            float xs[4] = {xa.x, xa.y, xa.z, xa.w};
            #pragma unroll
            for (int i = 0; i < 4; i++) {
                acc[i][0] = fmaf(xs[i], yb.x, acc[i][0]);
                acc[i][1] = fmaf(xs[i], yb.y, acc[i][1]);
            }
        }
        int base = grp * 1024;
        #pragma unroll
        for (int i = 0; i < 4; i++)
            *(float2*)&outp[base + (a0 + i) * 32 + b0] =
                make_float2(acc[i][0], acc[i][1]);
    } else {
        // persist normalized Q/K (512 float4 over 128 threads) + Ksum
        #pragma unroll
        for (int i = t; i < 512; i += 128) {
            int ten = i >> 8, idx = i & 255;
            int r4 = idx >> 3, c4 = (idx & 7) * 4;
            int g = ((c * 32 + r4) * H + h) * 32 + c4;
            if (ten == 0) *(float4*)&g_Qn[g] = *(const float4*)&sQ[r4][c4];
            else          *(float4*)&g_Kn[g] = *(const float4*)&sK[r4][c4];
        }
        if (t < 32) {
            float s = 0.0f;
            #pragma unroll
            for (int r = 0; r < 32; r++) s += sK[r][t];
            outp[3072 + t] = s;
        }
    }
}

// ---------------------------------------------------------------------------
// K2: 32 CTAs (4 per head). Coalesced 16-way reduce into g_mats.
// ---------------------------------------------------------------------------
__global__ __launch_bounds__(256) void k2_reduce() {
    int h = blockIdx.x & 7, p = blockIdx.x >> 3;   // head, quarter
    int tid = threadIdx.x;
    if (tid >= 194) return;
    int f4 = p * 194 + tid;                        // float4 index in [0,776)
    float4 s = make_float4(0.f, 0.f, 0.f, 0.f);
    #pragma unroll
    for (int cc = 0; cc < NCH; cc++) {
        const float4* pp = (const float4*)&g_part[((size_t)(cc * 8 + h)) * MATS];
        float4 a = pp[f4];
        s.x += a.x; s.y += a.y; s.z += a.z; s.w += a.w;
    }
    ((float4*)&g_mats[(size_t)h * MATS])[f4] = s;
}

// ---------------------------------------------------------------------------
// K3: 128 CTAs x 512 thr. GEMM epilogue: T1 = Q*KK, T2 = K*SQQ, O1 = Q*KV
// (4x2 register tiles, 128 thr each), then per-row dots (16 warps x 2 rows).
// ---------------------------------------------------------------------------
__global__ __launch_bounds__(512) void k3_consume(
        const float* __restrict__ v, float* __restrict__ out) {
    __shared__ __align__(16) float sQt[32][36];  // transposed: sQt[d][l]
    __shared__ __align__(16) float sKt[32][36];  // transposed: sKt[d][l]
    __shared__ __align__(16) float sV [32][36];  // row-major
    __shared__ __align__(16) float sM [MATS];    // KK | SQQ | KV | Ksum
    __shared__ __align__(16) float sT1[32][36];  // (Q*KK)[l][e]
    __shared__ __align__(16) float sT2[32][36];  // (K*SQQ)[l][e]
    __shared__ __align__(16) float sO1[32][36];  // (Q*KV)[l][m]

    int bx = blockIdx.x;
    int h = bx & 7, c = bx >> 3;
    int tid = threadIdx.x, lane = tid & 31, w = tid >> 5;

    // ---- stage matrices (776 float4 over 512 threads) ----
    {
        const float4* m4 = (const float4*)&g_mats[(size_t)h * MATS];
        float4* s4 = (float4*)sM;
        #pragma unroll
        for (int i = tid; i < MATS / 4; i += 512) s4[i] = m4[i];
    }
    // ---- load Q/K (transpose via STS) and V ----
    #pragma unroll
    for (int i = tid; i < 768; i += 512) {
        int ten = i >> 8, idx = i & 255;
        int r4 = idx >> 3, c4 = (idx & 7) * 4;
        int g = ((c * 32 + r4) * H + h) * 32 + c4;
        if (ten == 2) {
            *(float4*)&sV[r4][c4] = *(const float4*)&v[g];
        } else {
            float4 x = (ten == 0) ? *(const float4*)&g_Qn[g]
                                  : *(const float4*)&g_Kn[g];
            float (*T)[36] = (ten == 0) ? sQt : sKt;
            T[c4 + 0][r4] = x.x; T[c4 + 1][r4] = x.y;
            T[c4 + 2][r4] = x.z; T[c4 + 3][r4] = x.w;
        }
    }
    __syncthreads();

    // ---- 3 GEMMs: C[a][b] = sum_d X[d][a] * Y[d][b], 4x2 tiles ----
    int grp = tid >> 7, t = tid & 127;
    if (grp < 3) {
        const float (*X)[36] = (grp == 1) ? sKt : sQt;   // T1:Q, T2:K, O1:Q
        const float* Y = &sM[grp * 1024];
        float (*C)[36] = (grp == 0) ? sT1 : (grp == 1) ? sT2 : sO1;
        int a0 = (t & 7) * 4, b0 = (t >> 3) * 2;
        float acc[4][2] = {};
        #pragma unroll 4
        for (int d = 0; d < 32; d++) {
            float4 xa = *(const float4*)&X[d][a0];
            float2 yb = *(const float2*)&Y[d * 32 + b0];
            float xs[4] = {xa.x, xa.y, xa.z, xa.w};
            #pragma unroll
            for (int i = 0; i < 4; i++) {
                acc[i][0] = fmaf(xs[i], yb.x, acc[i][0]);
                acc[i][1] = fmaf(xs[i], yb.y, acc[i][1]);
            }
        }
        #pragma unroll
        for (int i = 0; i < 4; i++)
            *(float2*)&C[a0 + i][b0] = make_float2(acc[i][0], acc[i][1]);
    }
    __syncthreads();

    // ---- per-row finish: warp w -> rows 2w, 2w+1 ----
    #pragma unroll
    for (int rr = 0; rr < 2; rr++) {
        int r = w * 2 + rr;
        float ql = sQt[lane][r];
        float kl = sKt[lane][r];
        float tn = ql * fmaf(0.5f, sT1[r][lane], sM[3072 + lane]);
        float tc = 0.5f * kl * sT2[r][lane];
        #pragma unroll
        for (int o = 16; o; o >>= 1) {
            tn += __shfl_xor_sync(FULL, tn, o);
            tc += __shfl_xor_sync(FULL, tc, o);
        }
        int l = c * 32 + r;
        out[(l * H + h) * 32 + lane] =
            (sO1[r][lane] + tc * sV[r][lane]) / tn;
    }
}

extern "C" void kernel_launch(void* const* d_in, const int* in_sizes, int n_in,
                              void* d_out, int out_size) {
    const float* q    = (const float*)d_in[0];
    const float* k    = (const float*)d_in[1];
    const float* v    = (const float*)d_in[2];
    // d_in[3] attn_mask, d_in[4] query_lengths: unused by the reference
    const float* klen = (const float*)d_in[5];
    float* out = (float*)d_out;

    k1_build<<<NCH * H, 512>>>(q, k, v, klen);   // 128 CTAs
    k2_reduce<<<4 * H, 256>>>();                 // 32 CTAs
    k3_consume<<<NCH * H, 512>>>(v, out);        // 128 CTAs
}